// round 10
// baseline (speedup 1.0000x reference)
#include <cuda_runtime.h>
#include <cuda_bf16.h>
#include <stdint.h>
#include <math.h>

#define EMBED 512
#define HEADS 8
#define HD 64
#define BB 4
#define SS 2048
#define MROWS (BB * SS) /* 8192 */
#define NBH (BB * HEADS) /* 32 */

// ------------------------- scratch (no allocs allowed) ----------------------
__device__ float g_v[(size_t)MROWS * EMBED];
__device__ float g_attn[(size_t)NBH * SS * SS];
__device__ float2 g_stats[(size_t)NBH * SS * 16]; // per-(row, colblk) partial (m, l)
__device__ float2 g_ml[(size_t)NBH * SS];         // final (m, 1/l)
__device__ __nv_bfloat16 g_tmph[(size_t)MROWS * EMBED];
__device__ __nv_bfloat16 g_tmpl[(size_t)MROWS * EMBED];
__device__ __nv_bfloat16 g_qh[(size_t)MROWS * EMBED];
__device__ __nv_bfloat16 g_ql[(size_t)MROWS * EMBED];
__device__ __nv_bfloat16 g_kh[(size_t)MROWS * EMBED];
__device__ __nv_bfloat16 g_kl[(size_t)MROWS * EMBED];
__device__ __nv_bfloat16 g_ctxh[(size_t)MROWS * EMBED];
__device__ __nv_bfloat16 g_ctxl[(size_t)MROWS * EMBED];
__device__ __nv_bfloat16 g_vth[(size_t)NBH * HD * SS];
__device__ __nv_bfloat16 g_vtl[(size_t)NBH * HD * SS];
__device__ __nv_bfloat16 g_wth[4 * EMBED * EMBED];
__device__ __nv_bfloat16 g_wtl[4 * EMBED * EMBED];

// ------------------------- helpers -----------------------------------------
__device__ __forceinline__ uint32_t smem_u32(const void* p) {
    uint32_t a;
    asm("{ .reg .u64 t; cvta.to.shared.u64 t, %1; cvt.u32.u64 %0, t; }" : "=r"(a) : "l"(p));
    return a;
}

#define LDSM_X4(r0, r1, r2, r3, a) \
    asm volatile("ldmatrix.sync.aligned.m8n8.x4.shared.b16 {%0,%1,%2,%3}, [%4];" \
                 : "=r"(r0), "=r"(r1), "=r"(r2), "=r"(r3) : "r"(a))

#define MMA_BF16(d, a0, a1, a2, a3, b0, b1) \
    asm volatile("mma.sync.aligned.m16n8k16.row.col.f32.bf16.bf16.f32 " \
                 "{%0,%1,%2,%3}, {%4,%5,%6,%7}, {%8,%9}, {%0,%1,%2,%3};" \
                 : "+f"((d)[0]), "+f"((d)[1]), "+f"((d)[2]), "+f"((d)[3]) \
                 : "r"(a0), "r"(a1), "r"(a2), "r"(a3), "r"(b0), "r"(b1))

__device__ __forceinline__ void split2(float a, float b, uint32_t& h, uint32_t& l) {
    __nv_bfloat16 ha = __float2bfloat16(a), hb = __float2bfloat16(b);
    float la = a - __bfloat162float(ha), lb = b - __bfloat162float(hb);
    __nv_bfloat16 lla = __float2bfloat16(la), llb = __float2bfloat16(lb);
    h = ((uint32_t)__bfloat16_as_ushort(hb) << 16) | (uint32_t)__bfloat16_as_ushort(ha);
    l = ((uint32_t)__bfloat16_as_ushort(llb) << 16) | (uint32_t)__bfloat16_as_ushort(lla);
}

#define TSTRB 144
#define TILE128B (128 * TSTRB) /* 18432 */

// ---------------------------------------------------------------------------
// Weight transpose + split
// ---------------------------------------------------------------------------
__global__ __launch_bounds__(256) void split_wT_kernel(
    const float* __restrict__ W, __nv_bfloat16* __restrict__ th, __nv_bfloat16* __restrict__ tl)
{
    __shared__ float tile[32][33];
    const int n0 = blockIdx.x * 32, k0 = blockIdx.y * 32;
    const int tx = threadIdx.x, ty = threadIdx.y;
    #pragma unroll
    for (int j = 0; j < 4; j++)
        tile[ty + j * 8][tx] = W[(size_t)(k0 + ty + j * 8) * EMBED + n0 + tx];
    __syncthreads();
    #pragma unroll
    for (int j = 0; j < 4; j++) {
        int nl = ty + j * 8;
        float f = tile[tx][nl];
        __nv_bfloat16 hb = __float2bfloat16(f);
        __nv_bfloat16 lb = __float2bfloat16(f - __bfloat162float(hb));
        size_t o = (size_t)(n0 + nl) * EMBED + k0 + tx;
        th[o] = hb;
        tl[o] = lb;
    }
}

// ---------------------------------------------------------------------------
// Elementwise fp32 -> bf16 hi/lo split
// ---------------------------------------------------------------------------
__global__ __launch_bounds__(256) void split_hl_kernel(
    const float4* __restrict__ x, uint2* __restrict__ hi, uint2* __restrict__ lo, int n4)
{
    int i = blockIdx.x * 256 + threadIdx.x;
    if (i >= n4) return;
    float4 f = x[i];
    uint32_t h0, l0, h1, l1;
    split2(f.x, f.y, h0, l0);
    split2(f.z, f.w, h1, l1);
    hi[i] = make_uint2(h0, h1);
    lo[i] = make_uint2(l0, l1);
}

// ---------------------------------------------------------------------------
// V transpose + split
// ---------------------------------------------------------------------------
__global__ __launch_bounds__(256) void split_vT_kernel(
    const float* __restrict__ v, __nv_bfloat16* __restrict__ vth, __nv_bfloat16* __restrict__ vtl)
{
    __shared__ float tile[32][33];
    const int bh = blockIdx.z, b = bh >> 3, h = bh & 7;
    const int s0 = blockIdx.x * 32, d0 = blockIdx.y * 32;
    const int tx = threadIdx.x, ty = threadIdx.y;
    #pragma unroll
    for (int j = 0; j < 4; j++) {
        int sl = ty + j * 8;
        tile[sl][tx] = v[(size_t)(b * SS + s0 + sl) * EMBED + h * HD + d0 + tx];
    }
    __syncthreads();
    #pragma unroll
    for (int j = 0; j < 4; j++) {
        int dl = ty + j * 8;
        float f = tile[tx][dl];
        __nv_bfloat16 hb = __float2bfloat16(f);
        __nv_bfloat16 lb = __float2bfloat16(f - __bfloat162float(hb));
        size_t o = ((size_t)bh * HD + d0 + dl) * SS + s0 + tx;
        vth[o] = hb;
        vtl[o] = lb;
    }
}

// ---------------------------------------------------------------------------
// Projection GEMM via mma.sync, split-bf16, K=512 (3 CTAs/SM).
// ---------------------------------------------------------------------------
#define PRJ_SMEM (4 * TILE128B) /* 73728 */
__global__ __launch_bounds__(256) void proj_mma(
    const __nv_bfloat16* __restrict__ ah, const __nv_bfloat16* __restrict__ al,
    const __nv_bfloat16* __restrict__ wth, const __nv_bfloat16* __restrict__ wtl,
    const float* __restrict__ bias,
    float* __restrict__ cf, __nv_bfloat16* __restrict__ ch, __nv_bfloat16* __restrict__ cl,
    int mode)
{
    extern __shared__ char smem[];
    const uint32_t sb = smem_u32(smem);
    const int tid = threadIdx.x, wid = tid >> 5, lane = tid & 31;
    const int row0 = blockIdx.y * 128, col0 = blockIdx.x * 128;
    const uint32_t OA_H = 0, OA_L = TILE128B, OB_H = 2 * TILE128B, OB_L = 3 * TILE128B;

    const int wm = wid >> 2, wn = wid & 3;
    float acc[4][4][4] = {};

    const uint32_t a_r = lane & 15, a_c = (lane >> 4) * 16;
    const uint32_t b_r = (lane & 7) + ((lane >> 4) & 1) * 8;
    const uint32_t b_c = ((lane >> 3) & 1) * 16;
    const int lrow = tid >> 1, lhalf = tid & 1;
    const uint32_t so = (uint32_t)lrow * TSTRB + lhalf * 64;

    for (int kc = 0; kc < EMBED; kc += 64) {
        __syncthreads();
        {
            size_t ao = (size_t)(row0 + lrow) * EMBED + kc + lhalf * 32;
            size_t bo = (size_t)(col0 + lrow) * EMBED + kc + lhalf * 32;
            const uint4* ahp = (const uint4*)(ah + ao);
            const uint4* alp = (const uint4*)(al + ao);
            const uint4* bhp = (const uint4*)(wth + bo);
            const uint4* blp = (const uint4*)(wtl + bo);
            #pragma unroll
            for (int i = 0; i < 4; i++) {
                *(uint4*)(smem + OA_H + so + i * 16) = ahp[i];
                *(uint4*)(smem + OA_L + so + i * 16) = alp[i];
                *(uint4*)(smem + OB_H + so + i * 16) = bhp[i];
                *(uint4*)(smem + OB_L + so + i * 16) = blp[i];
            }
        }
        __syncthreads();

        #pragma unroll
        for (int ks = 0; ks < 4; ks++) {
            const uint32_t kb = ks * 32;
            uint32_t a[4][4], bhf[2][4], blf[2][4];
            #pragma unroll
            for (int mf = 0; mf < 4; mf++) {
                uint32_t ad = sb + OA_H + (wm * 64 + mf * 16 + a_r) * TSTRB + kb + a_c;
                LDSM_X4(a[mf][0], a[mf][1], a[mf][2], a[mf][3], ad);
            }
            #pragma unroll
            for (int p = 0; p < 2; p++) {
                uint32_t bd = sb + OB_H + (wn * 32 + p * 16 + b_r) * TSTRB + kb + b_c;
                LDSM_X4(bhf[p][0], bhf[p][1], bhf[p][2], bhf[p][3], bd);
            }
            #pragma unroll
            for (int p = 0; p < 2; p++) {
                uint32_t bd = sb + OB_L + (wn * 32 + p * 16 + b_r) * TSTRB + kb + b_c;
                LDSM_X4(blf[p][0], blf[p][1], blf[p][2], blf[p][3], bd);
            }
            #pragma unroll
            for (int mf = 0; mf < 4; mf++)
                #pragma unroll
                for (int nf = 0; nf < 4; nf++) {
                    MMA_BF16(acc[mf][nf], a[mf][0], a[mf][1], a[mf][2], a[mf][3],
                             bhf[nf >> 1][(nf & 1) * 2], bhf[nf >> 1][(nf & 1) * 2 + 1]);
                    MMA_BF16(acc[mf][nf], a[mf][0], a[mf][1], a[mf][2], a[mf][3],
                             blf[nf >> 1][(nf & 1) * 2], blf[nf >> 1][(nf & 1) * 2 + 1]);
                }
            #pragma unroll
            for (int mf = 0; mf < 4; mf++) {
                uint32_t ad = sb + OA_L + (wm * 64 + mf * 16 + a_r) * TSTRB + kb + a_c;
                LDSM_X4(a[mf][0], a[mf][1], a[mf][2], a[mf][3], ad);
            }
            #pragma unroll
            for (int mf = 0; mf < 4; mf++)
                #pragma unroll
                for (int nf = 0; nf < 4; nf++)
                    MMA_BF16(acc[mf][nf], a[mf][0], a[mf][1], a[mf][2], a[mf][3],
                             bhf[nf >> 1][(nf & 1) * 2], bhf[nf >> 1][(nf & 1) * 2 + 1]);
        }
    }

    const int er = lane >> 2, ec = (lane & 3) * 2;
    #pragma unroll
    for (int mf = 0; mf < 4; mf++) {
        int r = row0 + wm * 64 + mf * 16 + er;
        #pragma unroll
        for (int nf = 0; nf < 4; nf++) {
            int c = col0 + wn * 32 + nf * 8 + ec;
            float b0 = bias[c], b1 = bias[c + 1];
            float v00 = acc[mf][nf][0] + b0, v01 = acc[mf][nf][1] + b1;
            float v10 = acc[mf][nf][2] + b0, v11 = acc[mf][nf][3] + b1;
            if (mode == 0) {
                *(float2*)&cf[(size_t)r * EMBED + c] = make_float2(v00, v01);
                *(float2*)&cf[(size_t)(r + 8) * EMBED + c] = make_float2(v10, v11);
            } else {
                uint32_t h0, l0, h1, l1;
                split2(v00, v01, h0, l0);
                split2(v10, v11, h1, l1);
                *(uint32_t*)&ch[(size_t)r * EMBED + c] = h0;
                *(uint32_t*)&cl[(size_t)r * EMBED + c] = l0;
                *(uint32_t*)&ch[(size_t)(r + 8) * EMBED + c] = h1;
                *(uint32_t*)&cl[(size_t)(r + 8) * EMBED + c] = l1;
            }
        }
    }
}

// ---------------------------------------------------------------------------
// Scores + per-block softmax partials (rowmax m, sumexp l over this 128-col blk)
// ---------------------------------------------------------------------------
#define SC_SMEM (4 * TILE128B) /* 73728 */
__global__ __launch_bounds__(256) void scores_mma(
    const __nv_bfloat16* __restrict__ qh, const __nv_bfloat16* __restrict__ ql,
    const __nv_bfloat16* __restrict__ kh, const __nv_bfloat16* __restrict__ kl,
    float* __restrict__ attn, float2* __restrict__ stats)
{
    extern __shared__ char smem[];
    const uint32_t sb = smem_u32(smem);
    const int tid = threadIdx.x, wid = tid >> 5, lane = tid & 31;
    const int bh = blockIdx.z, b = bh >> 3, h = bh & 7;
    const int row0 = blockIdx.y * 128, col0 = blockIdx.x * 128;
    const uint32_t OA_H = 0, OA_L = TILE128B, OB_H = 2 * TILE128B, OB_L = 3 * TILE128B;

    {
        const int lrow = tid >> 1, lhalf = tid & 1;
        size_t qo = (size_t)(b * SS + row0 + lrow) * EMBED + h * HD + lhalf * 32;
        size_t ko = (size_t)(b * SS + col0 + lrow) * EMBED + h * HD + lhalf * 32;
        const uint4* qhp = (const uint4*)(qh + qo);
        const uint4* qlp = (const uint4*)(ql + qo);
        const uint4* khp = (const uint4*)(kh + ko);
        const uint4* klp = (const uint4*)(kl + ko);
        const uint32_t so = (uint32_t)lrow * TSTRB + lhalf * 64;
        #pragma unroll
        for (int i = 0; i < 4; i++) {
            *(uint4*)(smem + OA_H + so + i * 16) = qhp[i];
            *(uint4*)(smem + OA_L + so + i * 16) = qlp[i];
            *(uint4*)(smem + OB_H + so + i * 16) = khp[i];
            *(uint4*)(smem + OB_L + so + i * 16) = klp[i];
        }
    }
    __syncthreads();

    const int wm = wid >> 2, wn = wid & 3;
    float acc[4][4][4] = {};
    const uint32_t a_r = lane & 15, a_c = (lane >> 4) * 16;
    const uint32_t b_r = (lane & 7) + ((lane >> 4) & 1) * 8;
    const uint32_t b_c = ((lane >> 3) & 1) * 16;

    #pragma unroll
    for (int ks = 0; ks < 4; ks++) {
        const uint32_t kb = ks * 32;
        uint32_t a[4][4], bhf[2][4], blf[2][4];
        #pragma unroll
        for (int mf = 0; mf < 4; mf++) {
            uint32_t ad = sb + OA_H + (wm * 64 + mf * 16 + a_r) * TSTRB + kb + a_c;
            LDSM_X4(a[mf][0], a[mf][1], a[mf][2], a[mf][3], ad);
        }
        #pragma unroll
        for (int p = 0; p < 2; p++) {
            uint32_t bd = sb + OB_H + (wn * 32 + p * 16 + b_r) * TSTRB + kb + b_c;
            LDSM_X4(bhf[p][0], bhf[p][1], bhf[p][2], bhf[p][3], bd);
        }
        #pragma unroll
        for (int p = 0; p < 2; p++) {
            uint32_t bd = sb + OB_L + (wn * 32 + p * 16 + b_r) * TSTRB + kb + b_c;
            LDSM_X4(blf[p][0], blf[p][1], blf[p][2], blf[p][3], bd);
        }
        #pragma unroll
        for (int mf = 0; mf < 4; mf++)
            #pragma unroll
            for (int nf = 0; nf < 4; nf++) {
                MMA_BF16(acc[mf][nf], a[mf][0], a[mf][1], a[mf][2], a[mf][3],
                         bhf[nf >> 1][(nf & 1) * 2], bhf[nf >> 1][(nf & 1) * 2 + 1]);
                MMA_BF16(acc[mf][nf], a[mf][0], a[mf][1], a[mf][2], a[mf][3],
                         blf[nf >> 1][(nf & 1) * 2], blf[nf >> 1][(nf & 1) * 2 + 1]);
            }
        #pragma unroll
        for (int mf = 0; mf < 4; mf++) {
            uint32_t ad = sb + OA_L + (wm * 64 + mf * 16 + a_r) * TSTRB + kb + a_c;
            LDSM_X4(a[mf][0], a[mf][1], a[mf][2], a[mf][3], ad);
        }
        #pragma unroll
        for (int mf = 0; mf < 4; mf++)
            #pragma unroll
            for (int nf = 0; nf < 4; nf++)
                MMA_BF16(acc[mf][nf], a[mf][0], a[mf][1], a[mf][2], a[mf][3],
                         bhf[nf >> 1][(nf & 1) * 2], bhf[nf >> 1][(nf & 1) * 2 + 1]);
    }

    float* outp = attn + (size_t)bh * SS * SS;
    const int er = lane >> 2, ec = (lane & 3) * 2;
    #pragma unroll
    for (int mf = 0; mf < 4; mf++) {
        int r = row0 + wm * 64 + mf * 16 + er;
        #pragma unroll
        for (int nf = 0; nf < 4; nf++) {
            int c = col0 + wn * 32 + nf * 8 + ec;
            *(float2*)&outp[(size_t)r * SS + c] =
                make_float2(acc[mf][nf][0] * 0.125f, acc[mf][nf][1] * 0.125f);
            *(float2*)&outp[(size_t)(r + 8) * SS + c] =
                make_float2(acc[mf][nf][2] * 0.125f, acc[mf][nf][3] * 0.125f);
        }
    }

    // ---- per-block (m, l) partials over the 128 cols of this block ----
    __syncthreads();
    float* maxbuf = (float*)smem;           // [128][4]
    float* mrow   = (float*)smem + 512;     // [128]
    float* sumbuf = (float*)smem + 640;     // [128][4]

    #pragma unroll
    for (int mf = 0; mf < 4; mf++) {
        int r1 = wm * 64 + mf * 16 + er;
        float v1 = -1e30f, v2 = -1e30f;
        #pragma unroll
        for (int nf = 0; nf < 4; nf++) {
            v1 = fmaxf(v1, fmaxf(acc[mf][nf][0], acc[mf][nf][1]));
            v2 = fmaxf(v2, fmaxf(acc[mf][nf][2], acc[mf][nf][3]));
        }
        v1 = fmaxf(v1, __shfl_xor_sync(0xffffffffu, v1, 1));
        v1 = fmaxf(v1, __shfl_xor_sync(0xffffffffu, v1, 2));
        v2 = fmaxf(v2, __shfl_xor_sync(0xffffffffu, v2, 1));
        v2 = fmaxf(v2, __shfl_xor_sync(0xffffffffu, v2, 2));
        if ((lane & 3) == 0) {
            maxbuf[r1 * 4 + wn] = v1 * 0.125f;
            maxbuf[(r1 + 8) * 4 + wn] = v2 * 0.125f;
        }
    }
    __syncthreads();
    if (tid < 128) {
        float m = fmaxf(fmaxf(maxbuf[tid * 4], maxbuf[tid * 4 + 1]),
                        fmaxf(maxbuf[tid * 4 + 2], maxbuf[tid * 4 + 3]));
        mrow[tid] = m;
    }
    __syncthreads();
    #pragma unroll
    for (int mf = 0; mf < 4; mf++) {
        int r1 = wm * 64 + mf * 16 + er;
        float m1 = mrow[r1], m2 = mrow[r1 + 8];
        float s1 = 0.f, s2 = 0.f;
        #pragma unroll
        for (int nf = 0; nf < 4; nf++) {
            s1 += __expf(acc[mf][nf][0] * 0.125f - m1) + __expf(acc[mf][nf][1] * 0.125f - m1);
            s2 += __expf(acc[mf][nf][2] * 0.125f - m2) + __expf(acc[mf][nf][3] * 0.125f - m2);
        }
        s1 += __shfl_xor_sync(0xffffffffu, s1, 1);
        s1 += __shfl_xor_sync(0xffffffffu, s1, 2);
        s2 += __shfl_xor_sync(0xffffffffu, s2, 1);
        s2 += __shfl_xor_sync(0xffffffffu, s2, 2);
        if ((lane & 3) == 0) {
            sumbuf[r1 * 4 + wn] = s1;
            sumbuf[(r1 + 8) * 4 + wn] = s2;
        }
    }
    __syncthreads();
    if (tid < 128) {
        float l = sumbuf[tid * 4] + sumbuf[tid * 4 + 1] + sumbuf[tid * 4 + 2] + sumbuf[tid * 4 + 3];
        stats[((size_t)bh * SS + row0 + tid) * 16 + blockIdx.x] = make_float2(mrow[tid], l);
    }
}

// ---------------------------------------------------------------------------
// Combine 16 column-block partials -> final (m, 1/l) per row
// ---------------------------------------------------------------------------
__global__ __launch_bounds__(256) void combine_stats(
    const float2* __restrict__ stats, float2* __restrict__ ml)
{
    int r = blockIdx.x * 256 + threadIdx.x;
    const float2* p = stats + (size_t)r * 16;
    float m = -1e30f;
    float2 v[16];
    #pragma unroll
    for (int i = 0; i < 16; i++) { v[i] = p[i]; m = fmaxf(m, v[i].x); }
    float l = 0.f;
    #pragma unroll
    for (int i = 0; i < 16; i++) l += v[i].y * __expf(v[i].x - m);
    ml[r] = make_float2(m, 1.0f / l);
}

// ---------------------------------------------------------------------------
// Fused normalize + attn-write + PV. Warp owns 16 rows x full context.
// ---------------------------------------------------------------------------
#define VSTRB 272
#define VT_TILE (64 * VSTRB)   /* 17408 */
#define PV_SMEM (2 * VT_TILE)  /* 34816 */
__global__ __launch_bounds__(256) void pv_fused(
    float* __restrict__ attn, const float2* __restrict__ ml,
    const __nv_bfloat16* __restrict__ vth, const __nv_bfloat16* __restrict__ vtl,
    __nv_bfloat16* __restrict__ ctxh, __nv_bfloat16* __restrict__ ctxl)
{
    extern __shared__ char smem[];
    const uint32_t sb = smem_u32(smem);
    const int tid = threadIdx.x, wid = tid >> 5, lane = tid & 31;
    const int bh = blockIdx.y, b = bh >> 3, h = bh & 7;
    const int row0 = blockIdx.x * 128;
    const int g = lane >> 2, t4 = lane & 3;
    const int warprow = row0 + wid * 16;

    float* ap = attn + (size_t)bh * SS * SS;
    const float2 ml1 = ml[(size_t)bh * SS + warprow + g];
    const float2 ml2 = ml[(size_t)bh * SS + warprow + g + 8];
    const float m1 = ml1.x, il1 = ml1.y, m2 = ml2.x, il2 = ml2.y;

    const __nv_bfloat16* bhp = vth + (size_t)bh * HD * SS;
    const __nv_bfloat16* blp = vtl + (size_t)bh * HD * SS;

    float accv[8][4] = {};

    const int vrow = tid >> 2, vq = tid & 3; // 4 threads/row, 32 bf16 each
    const uint32_t b_r = (lane & 7) + ((lane >> 4) & 1) * 8;
    const uint32_t b_c = ((lane >> 3) & 1) * 16;

    for (int tt = 0; tt < 16; tt++) {
        __syncthreads();
        {   // V^T tile: 64 d-rows x 128 s-cols, hi/lo (full coverage: 4x uint4/thread)
            size_t o = (size_t)vrow * SS + tt * 128 + vq * 32;
            uint4 h0 = *(const uint4*)(bhp + o),      h1 = *(const uint4*)(bhp + o + 8);
            uint4 h2 = *(const uint4*)(bhp + o + 16), h3 = *(const uint4*)(bhp + o + 24);
            uint4 l0 = *(const uint4*)(blp + o),      l1 = *(const uint4*)(blp + o + 8);
            uint4 l2 = *(const uint4*)(blp + o + 16), l3 = *(const uint4*)(blp + o + 24);
            uint32_t soff = vrow * VSTRB + vq * 64;
            *(uint4*)(smem + soff)      = h0;
            *(uint4*)(smem + soff + 16) = h1;
            *(uint4*)(smem + soff + 32) = h2;
            *(uint4*)(smem + soff + 48) = h3;
            *(uint4*)(smem + VT_TILE + soff)      = l0;
            *(uint4*)(smem + VT_TILE + soff + 16) = l1;
            *(uint4*)(smem + VT_TILE + soff + 32) = l2;
            *(uint4*)(smem + VT_TILE + soff + 48) = l3;
        }
        __syncthreads();

        // read s, normalize, write attn, split to hi/lo frags
        uint32_t ph[16][2], pl[16][2];
        #pragma unroll
        for (int nf = 0; nf < 16; nf++) {
            int col = tt * 128 + nf * 8 + t4 * 2;
            size_t o1 = (size_t)(warprow + g) * SS + col;
            size_t o2 = (size_t)(warprow + g + 8) * SS + col;
            float2 s1 = *(float2*)&ap[o1];
            float2 s2 = *(float2*)&ap[o2];
            float p00 = __expf(s1.x - m1) * il1, p01 = __expf(s1.y - m1) * il1;
            float p10 = __expf(s2.x - m2) * il2, p11 = __expf(s2.y - m2) * il2;
            *(float2*)&ap[o1] = make_float2(p00, p01);
            *(float2*)&ap[o2] = make_float2(p10, p11);
            split2(p00, p01, ph[nf][0], pl[nf][0]);
            split2(p10, p11, ph[nf][1], pl[nf][1]);
        }

        #pragma unroll
        for (int kc = 0; kc < 8; kc++) {
            const uint32_t ah0 = ph[2 * kc][0], ah1 = ph[2 * kc][1];
            const uint32_t ah2 = ph[2 * kc + 1][0], ah3 = ph[2 * kc + 1][1];
            const uint32_t al0 = pl[2 * kc][0], al1 = pl[2 * kc][1];
            const uint32_t al2 = pl[2 * kc + 1][0], al3 = pl[2 * kc + 1][1];
            #pragma unroll
            for (int p2 = 0; p2 < 4; p2++) {
                uint32_t bh4[4], bl4[4];
                uint32_t bd = sb + (p2 * 16 + b_r) * VSTRB + kc * 32 + b_c;
                LDSM_X4(bh4[0], bh4[1], bh4[2], bh4[3], bd);
                uint32_t bd2 = sb + VT_TILE + (p2 * 16 + b_r) * VSTRB + kc * 32 + b_c;
                LDSM_X4(bl4[0], bl4[1], bl4[2], bl4[3], bd2);
                MMA_BF16(accv[2 * p2],     ah0, ah1, ah2, ah3, bh4[0], bh4[1]);
                MMA_BF16(accv[2 * p2],     ah0, ah1, ah2, ah3, bl4[0], bl4[1]);
                MMA_BF16(accv[2 * p2],     al0, al1, al2, al3, bh4[0], bh4[1]);
                MMA_BF16(accv[2 * p2 + 1], ah0, ah1, ah2, ah3, bh4[2], bh4[3]);
                MMA_BF16(accv[2 * p2 + 1], ah0, ah1, ah2, ah3, bl4[2], bl4[3]);
                MMA_BF16(accv[2 * p2 + 1], al0, al1, al2, al3, bh4[2], bh4[3]);
            }
        }
    }

    // epilogue: ctx -> bf16 hi/lo
    #pragma unroll
    for (int nf = 0; nf < 8; nf++) {
        int c = nf * 8 + t4 * 2;
        uint32_t h0, l0, h1, l1;
        split2(accv[nf][0], accv[nf][1], h0, l0);
        split2(accv[nf][2], accv[nf][3], h1, l1);
        size_t o0 = (size_t)(b * SS + warprow + g) * EMBED + h * HD + c;
        size_t o1 = (size_t)(b * SS + warprow + g + 8) * EMBED + h * HD + c;
        *(uint32_t*)&ctxh[o0] = h0;
        *(uint32_t*)&ctxl[o0] = l0;
        *(uint32_t*)&ctxh[o1] = h1;
        *(uint32_t*)&ctxl[o1] = l1;
    }
}

// ---------------------------------------------------------------------------
extern "C" void kernel_launch(void* const* d_in, const int* in_sizes, int n_in,
                              void* d_out, int out_size)
{
    const float* query = (const float*)d_in[0];
    const float* key   = (const float*)d_in[1];
    const float* value = (const float*)d_in[2];
    const float* Wq = (const float*)d_in[3];
    const float* bq = (const float*)d_in[4];
    const float* Wk = (const float*)d_in[5];
    const float* bk = (const float*)d_in[6];
    const float* Wv = (const float*)d_in[7];
    const float* bv = (const float*)d_in[8];
    const float* Wo = (const float*)d_in[9];
    const float* bo = (const float*)d_in[10];
    float* out = (float*)d_out;

    const size_t out_elems  = (size_t)MROWS * EMBED;
    const size_t attn_elems = (size_t)NBH * SS * SS;
    const size_t wsz = (size_t)EMBED * EMBED;

    float *pv, *pattn;
    float2 *pstats, *pml;
    __nv_bfloat16 *ptmph, *ptmpl, *pqh, *pql, *pkh, *pkl, *pctxh, *pctxl, *pvth, *pvtl, *pwth, *pwtl;
    cudaGetSymbolAddress((void**)&pv,    g_v);
    cudaGetSymbolAddress((void**)&pattn, g_attn);
    cudaGetSymbolAddress((void**)&pstats, g_stats);
    cudaGetSymbolAddress((void**)&pml,   g_ml);
    cudaGetSymbolAddress((void**)&ptmph, g_tmph);
    cudaGetSymbolAddress((void**)&ptmpl, g_tmpl);
    cudaGetSymbolAddress((void**)&pqh,   g_qh);
    cudaGetSymbolAddress((void**)&pql,   g_ql);
    cudaGetSymbolAddress((void**)&pkh,   g_kh);
    cudaGetSymbolAddress((void**)&pkl,   g_kl);
    cudaGetSymbolAddress((void**)&pctxh, g_ctxh);
    cudaGetSymbolAddress((void**)&pctxl, g_ctxl);
    cudaGetSymbolAddress((void**)&pvth,  g_vth);
    cudaGetSymbolAddress((void**)&pvtl,  g_vtl);
    cudaGetSymbolAddress((void**)&pwth,  g_wth);
    cudaGetSymbolAddress((void**)&pwtl,  g_wtl);

    float* attn = ((size_t)out_size >= out_elems + attn_elems) ? (out + out_elems) : pattn;

    cudaFuncSetAttribute(proj_mma, cudaFuncAttributeMaxDynamicSharedMemorySize, PRJ_SMEM);
    cudaFuncSetAttribute(scores_mma, cudaFuncAttributeMaxDynamicSharedMemorySize, SC_SMEM);
    cudaFuncSetAttribute(pv_fused, cudaFuncAttributeMaxDynamicSharedMemorySize, PV_SMEM);

    dim3 gW(EMBED / 32, EMBED / 32);
    split_wT_kernel<<<gW, dim3(32, 8)>>>(Wq, pwth + 0 * wsz, pwtl + 0 * wsz);
    split_wT_kernel<<<gW, dim3(32, 8)>>>(Wk, pwth + 1 * wsz, pwtl + 1 * wsz);
    split_wT_kernel<<<gW, dim3(32, 8)>>>(Wv, pwth + 2 * wsz, pwtl + 2 * wsz);
    split_wT_kernel<<<gW, dim3(32, 8)>>>(Wo, pwth + 3 * wsz, pwtl + 3 * wsz);

    const int n4 = (MROWS * EMBED) / 4;
    dim3 gP(EMBED / 128, MROWS / 128);

    split_hl_kernel<<<n4 / 256, 256>>>((const float4*)query, (uint2*)ptmph, (uint2*)ptmpl, n4);
    proj_mma<<<gP, 256, PRJ_SMEM>>>(ptmph, ptmpl, pwth + 0 * wsz, pwtl + 0 * wsz, bq,
                                    nullptr, pqh, pql, 1);
    split_hl_kernel<<<n4 / 256, 256>>>((const float4*)key, (uint2*)ptmph, (uint2*)ptmpl, n4);
    proj_mma<<<gP, 256, PRJ_SMEM>>>(ptmph, ptmpl, pwth + 1 * wsz, pwtl + 1 * wsz, bk,
                                    nullptr, pkh, pkl, 1);
    split_hl_kernel<<<n4 / 256, 256>>>((const float4*)value, (uint2*)ptmph, (uint2*)ptmpl, n4);
    proj_mma<<<gP, 256, PRJ_SMEM>>>(ptmph, ptmpl, pwth + 2 * wsz, pwtl + 2 * wsz, bv,
                                    pv, nullptr, nullptr, 0);
    split_vT_kernel<<<dim3(SS / 32, HD / 32, NBH), dim3(32, 8)>>>(pv, pvth, pvtl);

    scores_mma<<<dim3(SS / 128, SS / 128, NBH), 256, SC_SMEM>>>(pqh, pql, pkh, pkl, attn, pstats);

    combine_stats<<<(NBH * SS) / 256, 256>>>(pstats, pml);

    pv_fused<<<dim3(SS / 128, NBH), 256, PV_SMEM>>>(attn, pml, pvth, pvtl, pctxh, pctxl);

    proj_mma<<<gP, 256, PRJ_SMEM>>>(pctxh, pctxl, pwth + 3 * wsz, pwtl + 3 * wsz, bo,
                                    out, nullptr, nullptr, 0);
}